// round 7
// baseline (speedup 1.0000x reference)
#include <cuda_runtime.h>
#include <stdint.h>
#include <math.h>

#define HH 1280
#define WW 1920
#define BB 2
#define OH 427
#define OW 640
#define SENT2 0x7FFF7FFFu   // sentinel coords (32767,32767): loses to every real seed

// Scratch (device globals: allocation-free rule)
__device__ float    g_depth[BB][HH * WW];          // 19.6 MB
__device__ uint32_t g_near[2][BB][HH * WW];        // 2 x 19.6 MB, ping-pong
__device__ float    g_full[BB][2][HH * WW];        // filled + dist, 39.3 MB

// ---------------------------------------------------------------------------
// XLA fused-emitter dot: separate multiplies, k-ascending adds, NO fma.
__device__ __forceinline__ float dot3_nofma(float a0, float a1, float a2,
                                            float b0, float b1, float b2) {
    float p0 = __fmul_rn(a0, b0);
    float p1 = __fmul_rn(a1, b1);
    float p2 = __fmul_rn(a2, b2);
    return __fadd_rn(__fadd_rn(p0, p1), p2);
}

// winner select, branch-free: packed |dr|,|dc| via vabsdiff2, exact int dist.
// ij = (i<<16)|j. Sentinel 0x7FFF7FFF -> dist ~1.9e9 (fits u32, > any real 5.3e6,
// sentinel-vs-sentinel equal -> strict '<' keeps cur). Matches reference BIG math.
__device__ __forceinline__ uint32_t jfa_better(uint32_t cur, uint32_t cand, uint32_t ij) {
    unsigned a = __vabsdiffs2(ij, cur);
    unsigned b = __vabsdiffs2(ij, cand);
    unsigned da = (a >> 16) * (a >> 16) + (a & 0xFFFFu) * (a & 0xFFFFu);
    unsigned db = (b >> 16) * (b >> 16) + (b & 0xFFFFu) * (b & 0xFFFFu);
    return (db < da) ? cand : cur;
}

// ---------------------------------------------------------------------------
// 1) zero depth canvas
__global__ void zero_depth_kernel(int nb) {
    int t = blockIdx.x * blockDim.x + threadIdx.x;
    int total = nb * HH * WW / 4;
    if (t < total) reinterpret_cast<float4*>(g_depth)[t] = make_float4(0.f, 0.f, 0.f, 0.f);
}

// ---------------------------------------------------------------------------
// 2) project points, scatter-add depth (duplicates sum, like reference)
__global__ void scatter_kernel(const float* __restrict__ pts,
                               const float* __restrict__ pose,
                               const float* __restrict__ ext,
                               const float* __restrict__ intr,
                               int N) {
    int idx = blockIdx.x * blockDim.x + threadIdx.x;
    int b = blockIdx.y;
    if (idx >= N) return;
    const float* p = pts + ((size_t)b * N + idx) * 3;
    float x = p[0], y = p[1], z = p[2];
    const float* P = pose + b * 16;
    const float* E = ext + b * 16;
    const float* K = intr + b * 9;
    float wx = __fadd_rn(dot3_nofma(x, y, z, P[0], P[1], P[2]),  P[3]);
    float wy = __fadd_rn(dot3_nofma(x, y, z, P[4], P[5], P[6]),  P[7]);
    float wz = __fadd_rn(dot3_nofma(x, y, z, P[8], P[9], P[10]), P[11]);
    float cx = __fadd_rn(dot3_nofma(wx, wy, wz, E[0], E[1], E[2]),  E[3]);
    float cy = __fadd_rn(dot3_nofma(wx, wy, wz, E[4], E[5], E[6]),  E[7]);
    float cz = __fadd_rn(dot3_nofma(wx, wy, wz, E[8], E[9], E[10]), E[11]);
    float pu = dot3_nofma(cx, cy, cz, K[0], K[1], K[2]);
    float pv = dot3_nofma(cx, cy, cz, K[3], K[4], K[5]);
    float pw = dot3_nofma(cx, cy, cz, K[6], K[7], K[8]);
    float u = __fdiv_rn(pu, pw);
    float v = __fdiv_rn(pv, pw);
    int r = (int)floorf(v);
    int c = (int)floorf(u);
    if (r >= 0 && r < HH && c >= 0 && c < WW) {
        float x2 = __fmul_rn(x, x);
        float y2 = __fmul_rn(y, y);
        float z2 = __fmul_rn(z, z);
        float d = __fsqrt_rn(__fadd_rn(__fadd_rn(x2, y2), z2));
        atomicAdd(&g_depth[b][r * WW + c], d);
    }
}

// ---------------------------------------------------------------------------
// 3) init nearest: valid pixels seed themselves, else sentinel
__global__ void init_near_kernel(int nb) {
    int t = blockIdx.x * blockDim.x + threadIdx.x;
    int total = nb * HH * WW / 4;
    if (t >= total) return;
    float4 d = reinterpret_cast<const float4*>(g_depth)[t];
    int lin = t * 4;
    int pix = lin % (HH * WW);
    int i = pix / WW;
    int j0 = pix % WW;
    uint4 o;
    o.x = (d.x != 0.f) ? (uint32_t)((i << 16) | (j0 + 0)) : SENT2;
    o.y = (d.y != 0.f) ? (uint32_t)((i << 16) | (j0 + 1)) : SENT2;
    o.z = (d.z != 0.f) ? (uint32_t)((i << 16) | (j0 + 2)) : SENT2;
    o.w = (d.w != 0.f) ? (uint32_t)((i << 16) | (j0 + 3)) : SENT2;
    reinterpret_cast<uint4*>(g_near[0])[t] = o;
}

// ---------------------------------------------------------------------------
// 4) one JFA direction pass (global, runtime dy/dx; used for k >= 8).
__global__ void __launch_bounds__(480) jfa_pass_kernel(int srcSel, int dy, int dx) {
    const int b = blockIdx.z;
    const int i = blockIdx.y;
    const int j0 = threadIdx.x * 4;
    const uint32_t* __restrict__ s = g_near[srcSel][b];
    uint32_t* __restrict__ dpt = g_near[srcSel ^ 1][b];
    uint4 cur = *reinterpret_cast<const uint4*>(s + i * WW + j0);
    const int si = i - dy;
    const bool rowok = ((unsigned)si < (unsigned)HH);
    uint32_t candv[4];
    const int jb = j0 - dx;
    if (!rowok) {
        candv[0] = candv[1] = candv[2] = candv[3] = SENT2;
    } else if ((dx & 3) == 0) {
        if (jb >= 0 && jb + 3 < WW) {
            uint4 n = __ldg(reinterpret_cast<const uint4*>(s + si * WW + jb));
            candv[0] = n.x; candv[1] = n.y; candv[2] = n.z; candv[3] = n.w;
        } else {
#pragma unroll
            for (int t = 0; t < 4; t++) {
                int sj = jb + t;
                candv[t] = ((unsigned)sj < (unsigned)WW) ? __ldg(s + si * WW + sj) : SENT2;
            }
        }
    } else {
        int ws = jb & ~3;
        if (ws >= 0 && ws + 7 < WW) {
            uint4 n0 = __ldg(reinterpret_cast<const uint4*>(s + si * WW + ws));
            uint4 n1 = __ldg(reinterpret_cast<const uint4*>(s + si * WW + ws + 4));
            uint32_t w[8] = {n0.x, n0.y, n0.z, n0.w, n1.x, n1.y, n1.z, n1.w};
            int off = jb & 3;
#pragma unroll
            for (int t = 0; t < 4; t++) candv[t] = w[off + t];
        } else {
#pragma unroll
            for (int t = 0; t < 4; t++) {
                int sj = jb + t;
                candv[t] = ((unsigned)sj < (unsigned)WW) ? __ldg(s + si * WW + sj) : SENT2;
            }
        }
    }
    const uint32_t ijp = (uint32_t)((i << 16) | j0);
    uint32_t curv[4] = {cur.x, cur.y, cur.z, cur.w};
    uint32_t outv[4];
#pragma unroll
    for (int t = 0; t < 4; t++) outv[t] = jfa_better(curv[t], candv[t], ijp + t);
    *reinterpret_cast<uint4*>(dpt + i * WW + j0) = make_uint4(outv[0], outv[1], outv[2], outv[3]);
}

// ---------------------------------------------------------------------------
// 4b) fused row-local pair: (0,-k) then (0,+k), sequential, exact, in place.
__global__ void __launch_bounds__(480) jfa_rowpair_kernel(int srcSel, int k) {
    __shared__ uint32_t row[WW];
    const int b = blockIdx.z;
    const int i = blockIdx.y;
    uint32_t* __restrict__ s = g_near[srcSel][b] + i * WW;
    const int j0 = threadIdx.x * 4;
    uint4 v = *reinterpret_cast<const uint4*>(s + j0);
    *reinterpret_cast<uint4*>(row + j0) = v;
    uint32_t curv[4] = {v.x, v.y, v.z, v.w};
    const uint32_t ijp = (uint32_t)((i << 16) | j0);
    __syncthreads();

    uint32_t nv[4];
    {
        int jb = j0 + k;
        uint32_t candv[4];
        if ((k & 3) == 0 && jb + 3 < WW) {
            uint4 n = *reinterpret_cast<const uint4*>(row + jb);
            candv[0] = n.x; candv[1] = n.y; candv[2] = n.z; candv[3] = n.w;
        } else {
#pragma unroll
            for (int t = 0; t < 4; t++) candv[t] = (jb + t < WW) ? row[jb + t] : SENT2;
        }
#pragma unroll
        for (int t = 0; t < 4; t++) nv[t] = jfa_better(curv[t], candv[t], ijp + t);
    }
    __syncthreads();
    *reinterpret_cast<uint4*>(row + j0) = make_uint4(nv[0], nv[1], nv[2], nv[3]);
    __syncthreads();

    uint32_t ov[4];
    {
        int jb = j0 - k;
        uint32_t candv[4];
        if ((k & 3) == 0 && jb >= 0) {
            uint4 n = *reinterpret_cast<const uint4*>(row + jb);
            candv[0] = n.x; candv[1] = n.y; candv[2] = n.z; candv[3] = n.w;
        } else {
#pragma unroll
            for (int t = 0; t < 4; t++) candv[t] = (jb + t >= 0) ? row[jb + t] : SENT2;
        }
#pragma unroll
        for (int t = 0; t < 4; t++) ov[t] = jfa_better(nv[t], candv[t], ijp + t);
    }
    *reinterpret_cast<uint4*>(s + j0) = make_uint4(ov[0], ov[1], ov[2], ov[3]);
}

// ---------------------------------------------------------------------------
// 4c) fully fused step for small k: all 8 directions sequentially in smem.
//     Center 128x128 tile + halo H=8k (+ pad ring K of permanent sentinel).
//     After pass p, cells within ring H-p*k of center are exact -> center exact
//     after 8 passes. Out-of-image smem cells are kept SENT2 (load + masked STS),
//     so reads reproduce the reference's OOB -> BIG semantics exactly.
template <int K>
__global__ void __launch_bounds__((128 + 16 * K) * 4, 1) jfa_fused_t(int srcSel) {
    constexpr int H   = 8 * K;
    constexpr int TW  = 128 + 2 * H;   // computed tile width
    constexpr int TW2 = TW + 2 * K;    // + pad ring
    constexpr int NC  = TW / 4;        // cells per thread (rows ty+4c)
    extern __shared__ uint32_t sm[];
    const int b  = blockIdx.z;
    const int x0 = blockIdx.x * 128 - H;     // global col of computed col 0
    const int y0 = blockIdx.y * 128 - H;
    const int tx = threadIdx.x;              // 0..TW-1
    const int ty = threadIdx.y;              // 0..3
    const int tid = ty * TW + tx;
    const uint32_t* __restrict__ src = g_near[srcSel][b];
    uint32_t* __restrict__ dst = g_near[srcSel ^ 1][b];

    // pad ring := SENT2 (never rewritten; reads from it = reference OOB)
    for (int idx = tid; idx < K * TW2; idx += TW * 4) {
        int r = idx / TW2, c = idx % TW2;
        sm[r * TW2 + c] = SENT2;
        sm[(TW2 - 1 - r) * TW2 + c] = SENT2;
    }
    for (int idx = tid; idx < K * TW; idx += TW * 4) {
        int c = idx / TW, r = idx % TW;
        sm[(K + r) * TW2 + c] = SENT2;
        sm[(K + r) * TW2 + (TW2 - 1 - c)] = SENT2;
    }

    const int gj = x0 + tx;
    const bool okc = ((unsigned)gj < (unsigned)WW);
    const int giBase = y0 + ty;
    uint32_t* smBase = sm + (K + ty) * TW2 + (K + tx);
    uint32_t cur[NC];
#pragma unroll
    for (int c = 0; c < NC; c++) {
        int gi = giBase + 4 * c;
        uint32_t v = SENT2;
        if (okc && (unsigned)gi < (unsigned)HH) v = __ldg(src + gi * WW + gj);
        cur[c] = v;
        smBase[4 * c * TW2] = v;
    }
    const bool interior = (x0 >= 0) && (x0 + TW <= WW) && (y0 >= 0) && (y0 + TW <= HH);
    const uint32_t ijBase = ((uint32_t)giBase << 16) | (uint32_t)(gj & 0xFFFF);
    __syncthreads();

    // one direction: Jacobi read from smem (state p-1) into regs
    auto dir = [&](int DY, int DX) {
#pragma unroll
        for (int c = 0; c < NC; c++) {
            uint32_t cand = smBase[(4 * c - DY) * TW2 - DX];
            cur[c] = jfa_better(cur[c], cand, ijBase + ((uint32_t)(4 * c) << 16));
        }
    };
    // publish state: out-of-image cells forced back to SENT2
    auto publish = [&]() {
        __syncthreads();
        if (interior) {
#pragma unroll
            for (int c = 0; c < NC; c++) smBase[4 * c * TW2] = cur[c];
        } else {
#pragma unroll
            for (int c = 0; c < NC; c++) {
                bool ok = okc && ((unsigned)(giBase + 4 * c) < (unsigned)HH);
                smBase[4 * c * TW2] = ok ? cur[c] : SENT2;
            }
        }
        __syncthreads();
    };

    dir(-K, -K); publish();
    dir(-K,  0); publish();
    dir(-K,  K); publish();
    dir( 0, -K); publish();
    dir( 0,  K); publish();
    dir( K, -K); publish();
    dir( K,  0); publish();
    dir( K,  K);               // last: no publish, write center to gmem

    if (tx >= H && tx < H + 128) {
#pragma unroll
        for (int c = H / 4; c < H / 4 + 32; c++) {
            int gi = giBase + 4 * c;         // guaranteed in-image (center)
            dst[gi * WW + gj] = cur[c];
        }
    }
}

// ---------------------------------------------------------------------------
// 5) filled depth + distance map
__global__ void fill_kernel(int nb, int finalSel) {
    int t = blockIdx.x * blockDim.x + threadIdx.x;
    int total = nb * HH * WW;
    if (t >= total) return;
    int b = t / (HH * WW);
    int pix = t % (HH * WW);
    int i = pix / WW;
    int j = pix % WW;
    float dep = g_depth[b][pix];
    uint32_t nn = g_near[finalSel][b][pix];
    int nr = (int)(nn >> 16);     if (nr > HH - 1) nr = HH - 1;
    int nc = (int)(nn & 0xFFFFu); if (nc > WW - 1) nc = WW - 1;
    bool valid = (dep != 0.f);
    float filled = valid ? dep : g_depth[b][nr * WW + nc];
    float dr = __fadd_rn((float)i, -(float)nr);
    float dc = __fadd_rn((float)j, -(float)nc);
    float dist = valid ? 0.f : __fsqrt_rn(__fadd_rn(__fmul_rn(dr, dr), __fmul_rn(dc, dc)));
    g_full[b][0][pix] = filled;
    g_full[b][1][pix] = dist;
}

// ---------------------------------------------------------------------------
// 6) jax.image.resize(method='linear', antialias=True): separable triangle,
//    fp32 weights exactly as jax computes them, fp32 accumulation.
__global__ void resize_kernel(float* __restrict__ out, int nb) {
    int t = blockIdx.x * blockDim.x + threadIdx.x;
    int total = nb * 2 * OH * OW;
    if (t >= total) return;
    int ox = t % OW;
    int oy = (t / OW) % OH;
    int ch = (t / (OW * OH)) % 2;
    int b  =  t / (OW * OH * 2);

    const double s_h = (double)OH / (double)HH;
    const double s_w = (double)OW / (double)WW;
    const float inv_h = (float)(1.0 / s_h);
    const float inv_w = (float)(1.0 / s_w);

    float sfy = __fadd_rn(__fmul_rn(__fadd_rn((float)oy, 0.5f), inv_h), -0.5f);
    float sfx = __fadd_rn(__fmul_rn(__fadd_rn((float)ox, 0.5f), inv_w), -0.5f);

    int y0 = (int)ceilf(sfy - inv_h) - 1;  if (y0 < 0) y0 = 0;
    int y1 = (int)floorf(sfy + inv_h) + 1; if (y1 > HH - 1) y1 = HH - 1;
    int x0 = (int)ceilf(sfx - inv_w) - 1;  if (x0 < 0) x0 = 0;
    int x1 = (int)floorf(sfx + inv_w) + 1; if (x1 > WW - 1) x1 = WW - 1;

    float wx[10];
    float wxs = 0.0f;
    int nx = x1 - x0 + 1;
    if (nx > 10) nx = 10;
    for (int k = 0; k < nx; k++) {
        float d = fabsf(__fadd_rn(sfx, -(float)(x0 + k)));
        float xx = __fdiv_rn(d, inv_w);
        float w = __fadd_rn(1.0f, -xx);
        if (w < 0.0f) w = 0.0f;
        wx[k] = w;
        wxs = __fadd_rn(wxs, w);
    }
    for (int k = 0; k < nx; k++) wx[k] = __fdiv_rn(wx[k], wxs);

    const float* __restrict__ src = g_full[b][ch];
    float acc = 0.0f;
    float wys = 0.0f;
    float wy[10];
    int ny = y1 - y0 + 1;
    if (ny > 10) ny = 10;
    for (int k = 0; k < ny; k++) {
        float d = fabsf(__fadd_rn(sfy, -(float)(y0 + k)));
        float xx = __fdiv_rn(d, inv_h);
        float w = __fadd_rn(1.0f, -xx);
        if (w < 0.0f) w = 0.0f;
        wy[k] = w;
        wys = __fadd_rn(wys, w);
    }
    for (int k = 0; k < ny; k++) {
        float wyn = __fdiv_rn(wy[k], wys);
        const float* row = src + (y0 + k) * WW;
        float rowacc = 0.0f;
        for (int m = 0; m < nx; m++) {
            rowacc = __fmaf_rn(wx[m], row[x0 + m], rowacc);
        }
        acc = __fmaf_rn(wyn, rowacc, acc);
    }
    out[(((size_t)b * 2 + ch) * OH + oy) * OW + ox] = acc;
}

// ---------------------------------------------------------------------------
template <int K>
static void launch_fused(int srcSel, int nb) {
    constexpr int H = 8 * K;
    constexpr int TW = 128 + 2 * H;
    constexpr int TW2 = TW + 2 * K;
    size_t smem = (size_t)TW2 * TW2 * sizeof(uint32_t);
    cudaFuncSetAttribute(jfa_fused_t<K>, cudaFuncAttributeMaxDynamicSharedMemorySize, (int)smem);
    dim3 g(WW / 128, HH / 128, nb);
    dim3 bdim(TW, 4);
    jfa_fused_t<K><<<g, bdim, smem>>>(srcSel);
}

extern "C" void kernel_launch(void* const* d_in, const int* in_sizes, int n_in,
                              void* d_out, int out_size) {
    const float* pts  = (const float*)d_in[0];  // (B,N,3)
    const float* pose = (const float*)d_in[1];  // (B,4,4)
    const float* ext  = (const float*)d_in[2];  // (B,4,4)
    const float* intr = (const float*)d_in[3];  // (B,3,3)

    int nb = in_sizes[1] / 16;
    if (nb < 1) nb = 1;
    if (nb > BB) nb = BB;
    int N = in_sizes[0] / (nb * 3);

    int totalPix = nb * HH * WW;

    zero_depth_kernel<<<(totalPix / 4 + 255) / 256, 256>>>(nb);

    dim3 sg((N + 255) / 256, nb);
    scatter_kernel<<<sg, 256>>>(pts, pose, ext, intr, N);

    init_near_kernel<<<(totalPix / 4 + 255) / 256, 256>>>(nb);

    int src = 0;
    dim3 jg(1, HH, nb);

    // step k=1 (first): fully fused (flips buffer once)
    launch_fused<1>(src, nb); src ^= 1;

    // steps k = 1024..8: global passes + fused row pair, reference order
    static const int ks[8] = {1024, 512, 256, 128, 64, 32, 16, 8};
    for (int s = 0; s < 8; s++) {
        int k = ks[s];
        jfa_pass_kernel<<<jg, 480>>>(src, -k, -k); src ^= 1;
        jfa_pass_kernel<<<jg, 480>>>(src, -k,  0); src ^= 1;
        jfa_pass_kernel<<<jg, 480>>>(src, -k,  k); src ^= 1;
        jfa_rowpair_kernel<<<jg, 480>>>(src, k);
        jfa_pass_kernel<<<jg, 480>>>(src,  k, -k); src ^= 1;
        jfa_pass_kernel<<<jg, 480>>>(src,  k,  0); src ^= 1;
        jfa_pass_kernel<<<jg, 480>>>(src,  k,  k); src ^= 1;
    }

    // steps k = 4, 2, 1: fully fused
    launch_fused<4>(src, nb); src ^= 1;
    launch_fused<2>(src, nb); src ^= 1;
    launch_fused<1>(src, nb); src ^= 1;

    fill_kernel<<<(totalPix + 255) / 256, 256>>>(nb, src);

    int outTotal = nb * 2 * OH * OW;
    resize_kernel<<<(outTotal + 255) / 256, 256>>>((float*)d_out, nb);
}

// round 8
// speedup vs baseline: 1.1038x; 1.1038x over previous
#include <cuda_runtime.h>
#include <stdint.h>
#include <math.h>

#define HH 1280
#define WW 1920
#define BB 2
#define OH 427
#define OW 640
#define SENT2 0x7FFF7FFFu   // sentinel coords (32767,32767): loses to every real seed

// Scratch (device globals: allocation-free rule)
__device__ float    g_depth[BB][HH * WW];          // 19.6 MB
__device__ uint32_t g_near[2][BB][HH * WW];        // 2 x 19.6 MB, ping-pong
__device__ float    g_full[BB][2][HH * WW];        // filled + dist, 39.3 MB

// ---------------------------------------------------------------------------
// XLA fused-emitter dot: separate multiplies, k-ascending adds, NO fma.
__device__ __forceinline__ float dot3_nofma(float a0, float a1, float a2,
                                            float b0, float b1, float b2) {
    float p0 = __fmul_rn(a0, b0);
    float p1 = __fmul_rn(a1, b1);
    float p2 = __fmul_rn(a2, b2);
    return __fadd_rn(__fadd_rn(p0, p1), p2);
}

// winner select, branch-free: packed |dr|,|dc| via vabsdiff2, exact int dist.
// ij = (i<<16)|j. Sentinel 0x7FFF7FFF -> dist ~1.9e9 (fits u32, > any real 5.3e6,
// sentinel-vs-sentinel equal -> strict '<' keeps cur). Matches reference BIG math.
__device__ __forceinline__ uint32_t jfa_better(uint32_t cur, uint32_t cand, uint32_t ij) {
    unsigned a = __vabsdiffs2(ij, cur);
    unsigned b = __vabsdiffs2(ij, cand);
    unsigned da = (a >> 16) * (a >> 16) + (a & 0xFFFFu) * (a & 0xFFFFu);
    unsigned db = (b >> 16) * (b >> 16) + (b & 0xFFFFu) * (b & 0xFFFFu);
    return (db < da) ? cand : cur;
}

// ---------------------------------------------------------------------------
// 1) zero depth canvas
__global__ void zero_depth_kernel(int nb) {
    int t = blockIdx.x * blockDim.x + threadIdx.x;
    int total = nb * HH * WW / 4;
    if (t < total) reinterpret_cast<float4*>(g_depth)[t] = make_float4(0.f, 0.f, 0.f, 0.f);
}

// ---------------------------------------------------------------------------
// 2) project points, scatter-add depth (duplicates sum, like reference)
__global__ void scatter_kernel(const float* __restrict__ pts,
                               const float* __restrict__ pose,
                               const float* __restrict__ ext,
                               const float* __restrict__ intr,
                               int N) {
    int idx = blockIdx.x * blockDim.x + threadIdx.x;
    int b = blockIdx.y;
    if (idx >= N) return;
    const float* p = pts + ((size_t)b * N + idx) * 3;
    float x = p[0], y = p[1], z = p[2];
    const float* P = pose + b * 16;
    const float* E = ext + b * 16;
    const float* K = intr + b * 9;
    float wx = __fadd_rn(dot3_nofma(x, y, z, P[0], P[1], P[2]),  P[3]);
    float wy = __fadd_rn(dot3_nofma(x, y, z, P[4], P[5], P[6]),  P[7]);
    float wz = __fadd_rn(dot3_nofma(x, y, z, P[8], P[9], P[10]), P[11]);
    float cx = __fadd_rn(dot3_nofma(wx, wy, wz, E[0], E[1], E[2]),  E[3]);
    float cy = __fadd_rn(dot3_nofma(wx, wy, wz, E[4], E[5], E[6]),  E[7]);
    float cz = __fadd_rn(dot3_nofma(wx, wy, wz, E[8], E[9], E[10]), E[11]);
    float pu = dot3_nofma(cx, cy, cz, K[0], K[1], K[2]);
    float pv = dot3_nofma(cx, cy, cz, K[3], K[4], K[5]);
    float pw = dot3_nofma(cx, cy, cz, K[6], K[7], K[8]);
    float u = __fdiv_rn(pu, pw);
    float v = __fdiv_rn(pv, pw);
    int r = (int)floorf(v);
    int c = (int)floorf(u);
    if (r >= 0 && r < HH && c >= 0 && c < WW) {
        float x2 = __fmul_rn(x, x);
        float y2 = __fmul_rn(y, y);
        float z2 = __fmul_rn(z, z);
        float d = __fsqrt_rn(__fadd_rn(__fadd_rn(x2, y2), z2));
        atomicAdd(&g_depth[b][r * WW + c], d);
    }
}

// ---------------------------------------------------------------------------
// 3) init nearest: valid pixels seed themselves, else sentinel
__global__ void init_near_kernel(int nb) {
    int t = blockIdx.x * blockDim.x + threadIdx.x;
    int total = nb * HH * WW / 4;
    if (t >= total) return;
    float4 d = reinterpret_cast<const float4*>(g_depth)[t];
    int lin = t * 4;
    int pix = lin % (HH * WW);
    int i = pix / WW;
    int j0 = pix % WW;
    uint4 o;
    o.x = (d.x != 0.f) ? (uint32_t)((i << 16) | (j0 + 0)) : SENT2;
    o.y = (d.y != 0.f) ? (uint32_t)((i << 16) | (j0 + 1)) : SENT2;
    o.z = (d.z != 0.f) ? (uint32_t)((i << 16) | (j0 + 2)) : SENT2;
    o.w = (d.w != 0.f) ? (uint32_t)((i << 16) | (j0 + 3)) : SENT2;
    reinterpret_cast<uint4*>(g_near[0])[t] = o;
}

// ---------------------------------------------------------------------------
// 4) one JFA direction pass (global, runtime dy/dx — single symbol, warm I$).
//    Vectorized neighbor fetch: dx%4==0 -> aligned uint4; else two uint4 + select.
__global__ void __launch_bounds__(480) jfa_pass_kernel(int srcSel, int dy, int dx) {
    const int b = blockIdx.z;
    const int i = blockIdx.y;
    const int j0 = threadIdx.x * 4;
    const uint32_t* __restrict__ s = g_near[srcSel][b];
    uint32_t* __restrict__ dpt = g_near[srcSel ^ 1][b];
    uint4 cur = *reinterpret_cast<const uint4*>(s + i * WW + j0);
    const int si = i - dy;
    const bool rowok = ((unsigned)si < (unsigned)HH);
    uint32_t candv[4];
    const int jb = j0 - dx;                       // first source column
    if (!rowok) {
        candv[0] = candv[1] = candv[2] = candv[3] = SENT2;
    } else if ((dx & 3) == 0) {
        if (jb >= 0 && jb + 3 < WW) {
            uint4 n = __ldg(reinterpret_cast<const uint4*>(s + si * WW + jb));
            candv[0] = n.x; candv[1] = n.y; candv[2] = n.z; candv[3] = n.w;
        } else {
#pragma unroll
            for (int t = 0; t < 4; t++) {
                int sj = jb + t;
                candv[t] = ((unsigned)sj < (unsigned)WW) ? __ldg(s + si * WW + sj) : SENT2;
            }
        }
    } else {
        int ws = jb & ~3;                         // aligned window start
        if (ws >= 0 && ws + 7 < WW) {
            uint4 n0 = __ldg(reinterpret_cast<const uint4*>(s + si * WW + ws));
            uint4 n1 = __ldg(reinterpret_cast<const uint4*>(s + si * WW + ws + 4));
            uint32_t w[8] = {n0.x, n0.y, n0.z, n0.w, n1.x, n1.y, n1.z, n1.w};
            int off = jb & 3;
#pragma unroll
            for (int t = 0; t < 4; t++) candv[t] = w[off + t];
        } else {
#pragma unroll
            for (int t = 0; t < 4; t++) {
                int sj = jb + t;
                candv[t] = ((unsigned)sj < (unsigned)WW) ? __ldg(s + si * WW + sj) : SENT2;
            }
        }
    }
    const uint32_t ijp = (uint32_t)((i << 16) | j0);
    uint32_t curv[4] = {cur.x, cur.y, cur.z, cur.w};
    uint32_t outv[4];
#pragma unroll
    for (int t = 0; t < 4; t++) outv[t] = jfa_better(curv[t], candv[t], ijp + t);
    *reinterpret_cast<uint4*>(dpt + i * WW + j0) = make_uint4(outv[0], outv[1], outv[2], outv[3]);
}

// ---------------------------------------------------------------------------
// 4b) fused row-local pair: directions (0,-k) then (0,+k), sequential, exact.
//     Row i depends only on row i -> in place (parity of 2 passes = unchanged).
__global__ void __launch_bounds__(480) jfa_rowpair_kernel(int srcSel, int k) {
    __shared__ uint32_t row[WW];
    const int b = blockIdx.z;
    const int i = blockIdx.y;
    uint32_t* __restrict__ s = g_near[srcSel][b] + i * WW;
    const int j0 = threadIdx.x * 4;
    uint4 v = *reinterpret_cast<const uint4*>(s + j0);
    *reinterpret_cast<uint4*>(row + j0) = v;
    uint32_t curv[4] = {v.x, v.y, v.z, v.w};
    const uint32_t ijp = (uint32_t)((i << 16) | j0);
    __syncthreads();

    // direction (0,-k): cand = row[j + k]
    uint32_t nv[4];
    {
        int jb = j0 + k;
        uint32_t candv[4];
        if ((k & 3) == 0 && jb + 3 < WW) {
            uint4 n = *reinterpret_cast<const uint4*>(row + jb);
            candv[0] = n.x; candv[1] = n.y; candv[2] = n.z; candv[3] = n.w;
        } else if ((k & 3) != 0 && (jb & ~3) + 7 < WW) {
            int ws = jb & ~3;
            uint4 n0 = *reinterpret_cast<const uint4*>(row + ws);
            uint4 n1 = *reinterpret_cast<const uint4*>(row + ws + 4);
            uint32_t w[8] = {n0.x, n0.y, n0.z, n0.w, n1.x, n1.y, n1.z, n1.w};
            int off = jb & 3;
#pragma unroll
            for (int t = 0; t < 4; t++) candv[t] = w[off + t];
        } else {
#pragma unroll
            for (int t = 0; t < 4; t++) candv[t] = (jb + t < WW) ? row[jb + t] : SENT2;
        }
#pragma unroll
        for (int t = 0; t < 4; t++) nv[t] = jfa_better(curv[t], candv[t], ijp + t);
    }
    __syncthreads();           // all reads of stage-0 done
    *reinterpret_cast<uint4*>(row + j0) = make_uint4(nv[0], nv[1], nv[2], nv[3]);
    __syncthreads();           // stage-1 row visible

    // direction (0,+k): cand = row[j - k]
    uint32_t ov[4];
    {
        int jb = j0 - k;
        uint32_t candv[4];
        if ((k & 3) == 0 && jb >= 0) {
            uint4 n = *reinterpret_cast<const uint4*>(row + jb);
            candv[0] = n.x; candv[1] = n.y; candv[2] = n.z; candv[3] = n.w;
        } else if ((k & 3) != 0 && (jb & ~3) >= 0) {
            int ws = jb & ~3;
            uint4 n0 = *reinterpret_cast<const uint4*>(row + ws);
            uint4 n1 = *reinterpret_cast<const uint4*>(row + ws + 4);
            uint32_t w[8] = {n0.x, n0.y, n0.z, n0.w, n1.x, n1.y, n1.z, n1.w};
            int off = jb & 3;
#pragma unroll
            for (int t = 0; t < 4; t++) candv[t] = w[off + t];
        } else {
#pragma unroll
            for (int t = 0; t < 4; t++) candv[t] = (jb + t >= 0) ? row[jb + t] : SENT2;
        }
#pragma unroll
        for (int t = 0; t < 4; t++) ov[t] = jfa_better(nv[t], candv[t], ijp + t);
    }
    *reinterpret_cast<uint4*>(s + j0) = make_uint4(ov[0], ov[1], ov[2], ov[3]);
}

// ---------------------------------------------------------------------------
// 5) filled depth + distance map
__global__ void fill_kernel(int nb, int finalSel) {
    int t = blockIdx.x * blockDim.x + threadIdx.x;
    int total = nb * HH * WW;
    if (t >= total) return;
    int b = t / (HH * WW);
    int pix = t % (HH * WW);
    int i = pix / WW;
    int j = pix % WW;
    float dep = g_depth[b][pix];
    uint32_t nn = g_near[finalSel][b][pix];
    int nr = (int)(nn >> 16);     if (nr > HH - 1) nr = HH - 1;
    int nc = (int)(nn & 0xFFFFu); if (nc > WW - 1) nc = WW - 1;
    bool valid = (dep != 0.f);
    float filled = valid ? dep : g_depth[b][nr * WW + nc];
    float dr = __fadd_rn((float)i, -(float)nr);
    float dc = __fadd_rn((float)j, -(float)nc);
    float dist = valid ? 0.f : __fsqrt_rn(__fadd_rn(__fmul_rn(dr, dr), __fmul_rn(dc, dc)));
    g_full[b][0][pix] = filled;
    g_full[b][1][pix] = dist;
}

// ---------------------------------------------------------------------------
// 6) jax.image.resize(method='linear', antialias=True): separable triangle,
//    fp32 weights exactly as jax computes them, fp32 accumulation.
__global__ void resize_kernel(float* __restrict__ out, int nb) {
    int t = blockIdx.x * blockDim.x + threadIdx.x;
    int total = nb * 2 * OH * OW;
    if (t >= total) return;
    int ox = t % OW;
    int oy = (t / OW) % OH;
    int ch = (t / (OW * OH)) % 2;
    int b  =  t / (OW * OH * 2);

    const double s_h = (double)OH / (double)HH;
    const double s_w = (double)OW / (double)WW;
    const float inv_h = (float)(1.0 / s_h);
    const float inv_w = (float)(1.0 / s_w);

    float sfy = __fadd_rn(__fmul_rn(__fadd_rn((float)oy, 0.5f), inv_h), -0.5f);
    float sfx = __fadd_rn(__fmul_rn(__fadd_rn((float)ox, 0.5f), inv_w), -0.5f);

    int y0 = (int)ceilf(sfy - inv_h) - 1;  if (y0 < 0) y0 = 0;
    int y1 = (int)floorf(sfy + inv_h) + 1; if (y1 > HH - 1) y1 = HH - 1;
    int x0 = (int)ceilf(sfx - inv_w) - 1;  if (x0 < 0) x0 = 0;
    int x1 = (int)floorf(sfx + inv_w) + 1; if (x1 > WW - 1) x1 = WW - 1;

    float wx[10];
    float wxs = 0.0f;
    int nx = x1 - x0 + 1;
    if (nx > 10) nx = 10;
    for (int k = 0; k < nx; k++) {
        float d = fabsf(__fadd_rn(sfx, -(float)(x0 + k)));
        float xx = __fdiv_rn(d, inv_w);
        float w = __fadd_rn(1.0f, -xx);
        if (w < 0.0f) w = 0.0f;
        wx[k] = w;
        wxs = __fadd_rn(wxs, w);
    }
    for (int k = 0; k < nx; k++) wx[k] = __fdiv_rn(wx[k], wxs);

    const float* __restrict__ src = g_full[b][ch];
    float acc = 0.0f;
    float wys = 0.0f;
    float wy[10];
    int ny = y1 - y0 + 1;
    if (ny > 10) ny = 10;
    for (int k = 0; k < ny; k++) {
        float d = fabsf(__fadd_rn(sfy, -(float)(y0 + k)));
        float xx = __fdiv_rn(d, inv_h);
        float w = __fadd_rn(1.0f, -xx);
        if (w < 0.0f) w = 0.0f;
        wy[k] = w;
        wys = __fadd_rn(wys, w);
    }
    for (int k = 0; k < ny; k++) {
        float wyn = __fdiv_rn(wy[k], wys);
        const float* row = src + (y0 + k) * WW;
        float rowacc = 0.0f;
        for (int m = 0; m < nx; m++) {
            rowacc = __fmaf_rn(wx[m], row[x0 + m], rowacc);
        }
        acc = __fmaf_rn(wyn, rowacc, acc);
    }
    out[(((size_t)b * 2 + ch) * OH + oy) * OW + ox] = acc;
}

// ---------------------------------------------------------------------------
extern "C" void kernel_launch(void* const* d_in, const int* in_sizes, int n_in,
                              void* d_out, int out_size) {
    const float* pts  = (const float*)d_in[0];  // (B,N,3)
    const float* pose = (const float*)d_in[1];  // (B,4,4)
    const float* ext  = (const float*)d_in[2];  // (B,4,4)
    const float* intr = (const float*)d_in[3];  // (B,3,3)

    int nb = in_sizes[1] / 16;
    if (nb < 1) nb = 1;
    if (nb > BB) nb = BB;
    int N = in_sizes[0] / (nb * 3);

    int totalPix = nb * HH * WW;

    zero_depth_kernel<<<(totalPix / 4 + 255) / 256, 256>>>(nb);

    dim3 sg((N + 255) / 256, nb);
    scatter_kernel<<<sg, 256>>>(pts, pose, ext, intr, N);

    init_near_kernel<<<(totalPix / 4 + 255) / 256, 256>>>(nb);

    static const int steps[12] = {1, 1024, 512, 256, 128, 64, 32, 16, 8, 4, 2, 1};
    int src = 0;
    dim3 jg(1, HH, nb);
    for (int s = 0; s < 12; s++) {
        int k = steps[s];
        // dy = -k row: (-k,-k), (-k,0), (-k,k)
        jfa_pass_kernel<<<jg, 480>>>(src, -k, -k); src ^= 1;
        jfa_pass_kernel<<<jg, 480>>>(src, -k,  0); src ^= 1;
        jfa_pass_kernel<<<jg, 480>>>(src, -k,  k); src ^= 1;
        // dy = 0 pair fused, in place (parity unchanged): (0,-k) then (0,+k)
        jfa_rowpair_kernel<<<jg, 480>>>(src, k);
        // dy = +k row: (k,-k), (k,0), (k,k)
        jfa_pass_kernel<<<jg, 480>>>(src,  k, -k); src ^= 1;
        jfa_pass_kernel<<<jg, 480>>>(src,  k,  0); src ^= 1;
        jfa_pass_kernel<<<jg, 480>>>(src,  k,  k); src ^= 1;
    }

    fill_kernel<<<(totalPix + 255) / 256, 256>>>(nb, src);

    int outTotal = nb * 2 * OH * OW;
    resize_kernel<<<(outTotal + 255) / 256, 256>>>((float*)d_out, nb);
}

// round 9
// speedup vs baseline: 1.1505x; 1.0423x over previous
#include <cuda_runtime.h>
#include <stdint.h>
#include <math.h>

#define HH 1280
#define WW 1920
#define BB 2
#define OH 427
#define OW 640
#define SENT2 0x7FFF7FFFu   // sentinel coords (32767,32767): loses to every real seed

// Scratch (device globals: allocation-free rule)
__device__ float    g_depth[BB][HH * WW];          // 19.6 MB
__device__ uint32_t g_near[2][BB][HH * WW];        // 2 x 19.6 MB, ping-pong
__device__ float    g_full[BB][2][HH * WW];        // filled + dist, 39.3 MB

// ---------------------------------------------------------------------------
// XLA fused-emitter dot: separate multiplies, k-ascending adds, NO fma.
__device__ __forceinline__ float dot3_nofma(float a0, float a1, float a2,
                                            float b0, float b1, float b2) {
    float p0 = __fmul_rn(a0, b0);
    float p1 = __fmul_rn(a1, b1);
    float p2 = __fmul_rn(a2, b2);
    return __fadd_rn(__fadd_rn(p0, p1), p2);
}

// winner select, branch-free: packed |dr|,|dc| via vabsdiff2, exact int dist.
// ij = (i<<16)|j. Sentinel 0x7FFF7FFF -> dist ~1.9e9 (fits u32, > any real 5.3e6,
// sentinel-vs-sentinel equal -> strict '<' keeps cur). Matches reference BIG math.
__device__ __forceinline__ uint32_t jfa_better(uint32_t cur, uint32_t cand, uint32_t ij) {
    unsigned a = __vabsdiffs2(ij, cur);
    unsigned b = __vabsdiffs2(ij, cand);
    unsigned da = (a >> 16) * (a >> 16) + (a & 0xFFFFu) * (a & 0xFFFFu);
    unsigned db = (b >> 16) * (b >> 16) + (b & 0xFFFFu) * (b & 0xFFFFu);
    return (db < da) ? cand : cur;
}

// ---------------------------------------------------------------------------
// 1) zero depth canvas
__global__ void zero_depth_kernel(int nb) {
    int t = blockIdx.x * blockDim.x + threadIdx.x;
    int total = nb * HH * WW / 4;
    if (t < total) reinterpret_cast<float4*>(g_depth)[t] = make_float4(0.f, 0.f, 0.f, 0.f);
}

// ---------------------------------------------------------------------------
// 2) project points, scatter-add depth (duplicates sum, like reference)
__global__ void scatter_kernel(const float* __restrict__ pts,
                               const float* __restrict__ pose,
                               const float* __restrict__ ext,
                               const float* __restrict__ intr,
                               int N) {
    int idx = blockIdx.x * blockDim.x + threadIdx.x;
    int b = blockIdx.y;
    if (idx >= N) return;
    const float* p = pts + ((size_t)b * N + idx) * 3;
    float x = p[0], y = p[1], z = p[2];
    const float* P = pose + b * 16;
    const float* E = ext + b * 16;
    const float* K = intr + b * 9;
    float wx = __fadd_rn(dot3_nofma(x, y, z, P[0], P[1], P[2]),  P[3]);
    float wy = __fadd_rn(dot3_nofma(x, y, z, P[4], P[5], P[6]),  P[7]);
    float wz = __fadd_rn(dot3_nofma(x, y, z, P[8], P[9], P[10]), P[11]);
    float cx = __fadd_rn(dot3_nofma(wx, wy, wz, E[0], E[1], E[2]),  E[3]);
    float cy = __fadd_rn(dot3_nofma(wx, wy, wz, E[4], E[5], E[6]),  E[7]);
    float cz = __fadd_rn(dot3_nofma(wx, wy, wz, E[8], E[9], E[10]), E[11]);
    float pu = dot3_nofma(cx, cy, cz, K[0], K[1], K[2]);
    float pv = dot3_nofma(cx, cy, cz, K[3], K[4], K[5]);
    float pw = dot3_nofma(cx, cy, cz, K[6], K[7], K[8]);
    float u = __fdiv_rn(pu, pw);
    float v = __fdiv_rn(pv, pw);
    int r = (int)floorf(v);
    int c = (int)floorf(u);
    if (r >= 0 && r < HH && c >= 0 && c < WW) {
        float x2 = __fmul_rn(x, x);
        float y2 = __fmul_rn(y, y);
        float z2 = __fmul_rn(z, z);
        float d = __fsqrt_rn(__fadd_rn(__fadd_rn(x2, y2), z2));
        atomicAdd(&g_depth[b][r * WW + c], d);
    }
}

// ---------------------------------------------------------------------------
// 3) init nearest: valid pixels seed themselves, else sentinel
__global__ void init_near_kernel(int nb) {
    int t = blockIdx.x * blockDim.x + threadIdx.x;
    int total = nb * HH * WW / 4;
    if (t >= total) return;
    float4 d = reinterpret_cast<const float4*>(g_depth)[t];
    int lin = t * 4;
    int pix = lin % (HH * WW);
    int i = pix / WW;
    int j0 = pix % WW;
    uint4 o;
    o.x = (d.x != 0.f) ? (uint32_t)((i << 16) | (j0 + 0)) : SENT2;
    o.y = (d.y != 0.f) ? (uint32_t)((i << 16) | (j0 + 1)) : SENT2;
    o.z = (d.z != 0.f) ? (uint32_t)((i << 16) | (j0 + 2)) : SENT2;
    o.w = (d.w != 0.f) ? (uint32_t)((i << 16) | (j0 + 3)) : SENT2;
    reinterpret_cast<uint4*>(g_near[0])[t] = o;
}

// ---------------------------------------------------------------------------
// 4a) aligned JFA pass: dx % 4 == 0. jb = j0-dx is uint4-aligned, so the cand
//     window is ALL-in or ALL-out of the row -> zero per-lane masking, no
//     scalar fallback, branch-free body.
__global__ void __launch_bounds__(480) jfa_pass_a(int srcSel, int dy, int dx) {
    const int b = blockIdx.z;
    const int i = blockIdx.y;
    const int j0 = threadIdx.x * 4;
    const uint32_t* __restrict__ s = g_near[srcSel][b];
    uint32_t* __restrict__ dpt = g_near[srcSel ^ 1][b];
    uint4 cur = *reinterpret_cast<const uint4*>(s + i * WW + j0);
    const int si = i - dy;
    const int jb = j0 - dx;
    const bool ok = ((unsigned)si < (unsigned)HH) & ((unsigned)jb < (unsigned)WW);
    const uint4* p = reinterpret_cast<const uint4*>(s + (ok ? si * WW + jb : 0));
    uint4 n = __ldg(p);                      // safe addr even when !ok
    if (!ok) { n.x = SENT2; n.y = SENT2; n.z = SENT2; n.w = SENT2; }
    const uint32_t ijp = (uint32_t)((i << 16) | j0);
    uint32_t outv[4];
    uint32_t curv[4] = {cur.x, cur.y, cur.z, cur.w};
    uint32_t candv[4] = {n.x, n.y, n.z, n.w};
#pragma unroll
    for (int t = 0; t < 4; t++) outv[t] = jfa_better(curv[t], candv[t], ijp + t);
    *reinterpret_cast<uint4*>(dpt + i * WW + j0) = make_uint4(outv[0], outv[1], outv[2], outv[3]);
}

// ---------------------------------------------------------------------------
// 4b) small-dx JFA pass, DX compile-time in {-2,-1,1,2}: constexpr shuffle
//     offset -> pure register selects (no local memory), runtime dy.
template <int DX>
__global__ void __launch_bounds__(480) jfa_pass_s(int srcSel, int dy) {
    const int b = blockIdx.z;
    const int i = blockIdx.y;
    const int j0 = threadIdx.x * 4;
    const uint32_t* __restrict__ s = g_near[srcSel][b];
    uint32_t* __restrict__ dpt = g_near[srcSel ^ 1][b];
    uint4 cur = *reinterpret_cast<const uint4*>(s + i * WW + j0);
    const int si = i - dy;
    const int jb = j0 - DX;
    const int ws = jb & ~3;
    constexpr int off = (-DX) & 3;
    uint32_t candv[4];
    if (((unsigned)si < (unsigned)HH) && ws >= 0 && ws + 7 < WW) {
        const uint32_t* rp = s + si * WW;
        uint4 n0 = __ldg(reinterpret_cast<const uint4*>(rp + ws));
        uint4 n1 = __ldg(reinterpret_cast<const uint4*>(rp + ws + 4));
        uint32_t w[8] = {n0.x, n0.y, n0.z, n0.w, n1.x, n1.y, n1.z, n1.w};
#pragma unroll
        for (int t = 0; t < 4; t++) candv[t] = w[off + t];   // constexpr -> MOVs
    } else if ((unsigned)si < (unsigned)HH) {
#pragma unroll
        for (int t = 0; t < 4; t++) {
            int sj = jb + t;
            candv[t] = ((unsigned)sj < (unsigned)WW) ? __ldg(s + si * WW + sj) : SENT2;
        }
    } else {
        candv[0] = candv[1] = candv[2] = candv[3] = SENT2;
    }
    const uint32_t ijp = (uint32_t)((i << 16) | j0);
    uint32_t curv[4] = {cur.x, cur.y, cur.z, cur.w};
    uint32_t outv[4];
#pragma unroll
    for (int t = 0; t < 4; t++) outv[t] = jfa_better(curv[t], candv[t], ijp + t);
    *reinterpret_cast<uint4*>(dpt + i * WW + j0) = make_uint4(outv[0], outv[1], outv[2], outv[3]);
}

// ---------------------------------------------------------------------------
// 4c) fused C,D,E: directions (-k,+k), (0,-k), (0,+k), sequential & exact.
//     C reads pre-C rows i and i+k from gmem (true Jacobi); D,E are row-local
//     on the post-C row held in smem. Reads src, writes dst (one flip).
__global__ void __launch_bounds__(480) jfa_cde_kernel(int srcSel, int k) {
    __shared__ uint32_t row[WW];
    const int b = blockIdx.z;
    const int i = blockIdx.y;
    const int j0 = threadIdx.x * 4;
    const uint32_t* __restrict__ src = g_near[srcSel][b];
    uint32_t* __restrict__ dst = g_near[srcSel ^ 1][b];
    uint4 v = *reinterpret_cast<const uint4*>(src + i * WW + j0);
    uint32_t cur[4] = {v.x, v.y, v.z, v.w};
    const uint32_t ijp = (uint32_t)((i << 16) | j0);

    // C = (-k, +k): cand(i,j) = src(i+k, j-k)
    uint32_t cC[4];
    {
        const int si = i + k;
        const int jb = j0 - k;
        if ((unsigned)si < (unsigned)HH) {
            const uint32_t* rp = src + si * WW;
            if ((k & 3) == 0) {   // aligned: all-or-none window
                const bool ok = ((unsigned)jb < (unsigned)WW);
                uint4 n = __ldg(reinterpret_cast<const uint4*>(rp + (ok ? jb : 0)));
                if (!ok) { n.x = SENT2; n.y = SENT2; n.z = SENT2; n.w = SENT2; }
                cC[0] = n.x; cC[1] = n.y; cC[2] = n.z; cC[3] = n.w;
            } else {
#pragma unroll
                for (int t = 0; t < 4; t++) {
                    int sj = jb + t;
                    cC[t] = ((unsigned)sj < (unsigned)WW) ? __ldg(rp + sj) : SENT2;
                }
            }
        } else {
            cC[0] = cC[1] = cC[2] = cC[3] = SENT2;
        }
    }
    uint32_t v0[4];
#pragma unroll
    for (int t = 0; t < 4; t++) v0[t] = jfa_better(cur[t], cC[t], ijp + t);
    *reinterpret_cast<uint4*>(row + j0) = make_uint4(v0[0], v0[1], v0[2], v0[3]);
    __syncthreads();

    // D = (0, -k): cand = row[j + k]   (post-C)
    uint32_t v1[4];
    {
        const int jd = j0 + k;
        uint32_t cD[4];
        if ((k & 3) == 0 && jd + 3 < WW) {
            uint4 n = *reinterpret_cast<const uint4*>(row + jd);
            cD[0] = n.x; cD[1] = n.y; cD[2] = n.z; cD[3] = n.w;
        } else {
#pragma unroll
            for (int t = 0; t < 4; t++) cD[t] = (jd + t < WW) ? row[jd + t] : SENT2;
        }
#pragma unroll
        for (int t = 0; t < 4; t++) v1[t] = jfa_better(v0[t], cD[t], ijp + t);
    }
    __syncthreads();        // all D reads of post-C row done
    *reinterpret_cast<uint4*>(row + j0) = make_uint4(v1[0], v1[1], v1[2], v1[3]);
    __syncthreads();        // post-D row visible

    // E = (0, +k): cand = row[j - k]   (post-D)
    uint32_t outv[4];
    {
        const int je = j0 - k;
        uint32_t cE[4];
        if ((k & 3) == 0 && je >= 0) {
            uint4 n = *reinterpret_cast<const uint4*>(row + je);
            cE[0] = n.x; cE[1] = n.y; cE[2] = n.z; cE[3] = n.w;
        } else {
#pragma unroll
            for (int t = 0; t < 4; t++) cE[t] = (je + t >= 0) ? row[je + t] : SENT2;
        }
#pragma unroll
        for (int t = 0; t < 4; t++) outv[t] = jfa_better(v1[t], cE[t], ijp + t);
    }
    *reinterpret_cast<uint4*>(dst + i * WW + j0) = make_uint4(outv[0], outv[1], outv[2], outv[3]);
}

// ---------------------------------------------------------------------------
// 5) filled depth + distance map
__global__ void fill_kernel(int nb, int finalSel) {
    int t = blockIdx.x * blockDim.x + threadIdx.x;
    int total = nb * HH * WW;
    if (t >= total) return;
    int b = t / (HH * WW);
    int pix = t % (HH * WW);
    int i = pix / WW;
    int j = pix % WW;
    float dep = g_depth[b][pix];
    uint32_t nn = g_near[finalSel][b][pix];
    int nr = (int)(nn >> 16);     if (nr > HH - 1) nr = HH - 1;
    int nc = (int)(nn & 0xFFFFu); if (nc > WW - 1) nc = WW - 1;
    bool valid = (dep != 0.f);
    float filled = valid ? dep : g_depth[b][nr * WW + nc];
    float dr = __fadd_rn((float)i, -(float)nr);
    float dc = __fadd_rn((float)j, -(float)nc);
    float dist = valid ? 0.f : __fsqrt_rn(__fadd_rn(__fmul_rn(dr, dr), __fmul_rn(dc, dc)));
    g_full[b][0][pix] = filled;
    g_full[b][1][pix] = dist;
}

// ---------------------------------------------------------------------------
// 6) jax.image.resize(method='linear', antialias=True): separable triangle,
//    fp32 weights exactly as jax computes them, fp32 accumulation.
__global__ void resize_kernel(float* __restrict__ out, int nb) {
    int t = blockIdx.x * blockDim.x + threadIdx.x;
    int total = nb * 2 * OH * OW;
    if (t >= total) return;
    int ox = t % OW;
    int oy = (t / OW) % OH;
    int ch = (t / (OW * OH)) % 2;
    int b  =  t / (OW * OH * 2);

    const double s_h = (double)OH / (double)HH;
    const double s_w = (double)OW / (double)WW;
    const float inv_h = (float)(1.0 / s_h);
    const float inv_w = (float)(1.0 / s_w);

    float sfy = __fadd_rn(__fmul_rn(__fadd_rn((float)oy, 0.5f), inv_h), -0.5f);
    float sfx = __fadd_rn(__fmul_rn(__fadd_rn((float)ox, 0.5f), inv_w), -0.5f);

    int y0 = (int)ceilf(sfy - inv_h) - 1;  if (y0 < 0) y0 = 0;
    int y1 = (int)floorf(sfy + inv_h) + 1; if (y1 > HH - 1) y1 = HH - 1;
    int x0 = (int)ceilf(sfx - inv_w) - 1;  if (x0 < 0) x0 = 0;
    int x1 = (int)floorf(sfx + inv_w) + 1; if (x1 > WW - 1) x1 = WW - 1;

    float wx[10];
    float wxs = 0.0f;
    int nx = x1 - x0 + 1;
    if (nx > 10) nx = 10;
    for (int k = 0; k < nx; k++) {
        float d = fabsf(__fadd_rn(sfx, -(float)(x0 + k)));
        float xx = __fdiv_rn(d, inv_w);
        float w = __fadd_rn(1.0f, -xx);
        if (w < 0.0f) w = 0.0f;
        wx[k] = w;
        wxs = __fadd_rn(wxs, w);
    }
    for (int k = 0; k < nx; k++) wx[k] = __fdiv_rn(wx[k], wxs);

    const float* __restrict__ src = g_full[b][ch];
    float acc = 0.0f;
    float wys = 0.0f;
    float wy[10];
    int ny = y1 - y0 + 1;
    if (ny > 10) ny = 10;
    for (int k = 0; k < ny; k++) {
        float d = fabsf(__fadd_rn(sfy, -(float)(y0 + k)));
        float xx = __fdiv_rn(d, inv_h);
        float w = __fadd_rn(1.0f, -xx);
        if (w < 0.0f) w = 0.0f;
        wy[k] = w;
        wys = __fadd_rn(wys, w);
    }
    for (int k = 0; k < ny; k++) {
        float wyn = __fdiv_rn(wy[k], wys);
        const float* row = src + (y0 + k) * WW;
        float rowacc = 0.0f;
        for (int m = 0; m < nx; m++) {
            rowacc = __fmaf_rn(wx[m], row[x0 + m], rowacc);
        }
        acc = __fmaf_rn(wyn, rowacc, acc);
    }
    out[(((size_t)b * 2 + ch) * OH + oy) * OW + ox] = acc;
}

// ---------------------------------------------------------------------------
extern "C" void kernel_launch(void* const* d_in, const int* in_sizes, int n_in,
                              void* d_out, int out_size) {
    const float* pts  = (const float*)d_in[0];  // (B,N,3)
    const float* pose = (const float*)d_in[1];  // (B,4,4)
    const float* ext  = (const float*)d_in[2];  // (B,4,4)
    const float* intr = (const float*)d_in[3];  // (B,3,3)

    int nb = in_sizes[1] / 16;
    if (nb < 1) nb = 1;
    if (nb > BB) nb = BB;
    int N = in_sizes[0] / (nb * 3);

    int totalPix = nb * HH * WW;

    zero_depth_kernel<<<(totalPix / 4 + 255) / 256, 256>>>(nb);

    dim3 sg((N + 255) / 256, nb);
    scatter_kernel<<<sg, 256>>>(pts, pose, ext, intr, N);

    init_near_kernel<<<(totalPix / 4 + 255) / 256, 256>>>(nb);

    int src = 0;
    dim3 jg(1, HH, nb);

    // Per step, reference order: A=(-k,-k), B=(-k,0), [C=(-k,k), D=(0,-k),
    // E=(0,k)] fused, F=(k,-k), G=(k,0), H=(k,k).

    // aligned step (k % 4 == 0)
    auto stepA = [&](int k) {
        jfa_pass_a<<<jg, 480>>>(src, -k, -k); src ^= 1;   // A
        jfa_pass_a<<<jg, 480>>>(src, -k,  0); src ^= 1;   // B
        jfa_cde_kernel<<<jg, 480>>>(src, k);  src ^= 1;   // C,D,E
        jfa_pass_a<<<jg, 480>>>(src,  k, -k); src ^= 1;   // F
        jfa_pass_a<<<jg, 480>>>(src,  k,  0); src ^= 1;   // G
        jfa_pass_a<<<jg, 480>>>(src,  k,  k); src ^= 1;   // H
    };
    // k = 1 step
    auto step1 = [&]() {
        jfa_pass_s<-1><<<jg, 480>>>(src, -1); src ^= 1;   // A
        jfa_pass_a<<<jg, 480>>>(src, -1, 0);  src ^= 1;   // B
        jfa_cde_kernel<<<jg, 480>>>(src, 1);  src ^= 1;   // C,D,E
        jfa_pass_s<-1><<<jg, 480>>>(src, 1);  src ^= 1;   // F
        jfa_pass_a<<<jg, 480>>>(src, 1, 0);   src ^= 1;   // G
        jfa_pass_s<1><<<jg, 480>>>(src, 1);   src ^= 1;   // H
    };
    // k = 2 step
    auto step2 = [&]() {
        jfa_pass_s<-2><<<jg, 480>>>(src, -2); src ^= 1;   // A
        jfa_pass_a<<<jg, 480>>>(src, -2, 0);  src ^= 1;   // B
        jfa_cde_kernel<<<jg, 480>>>(src, 2);  src ^= 1;   // C,D,E
        jfa_pass_s<-2><<<jg, 480>>>(src, 2);  src ^= 1;   // F
        jfa_pass_a<<<jg, 480>>>(src, 2, 0);   src ^= 1;   // G
        jfa_pass_s<2><<<jg, 480>>>(src, 2);   src ^= 1;   // H
    };

    // schedule: 1, 1024, 512, 256, 128, 64, 32, 16, 8, 4, 2, 1
    step1();
    stepA(1024);
    stepA(512);
    stepA(256);
    stepA(128);
    stepA(64);
    stepA(32);
    stepA(16);
    stepA(8);
    stepA(4);
    step2();
    step1();

    fill_kernel<<<(totalPix + 255) / 256, 256>>>(nb, src);

    int outTotal = nb * 2 * OH * OW;
    resize_kernel<<<(outTotal + 255) / 256, 256>>>((float*)d_out, nb);
}